// round 16
// baseline (speedup 1.0000x reference)
#include <cuda_runtime.h>
#include <cstdint>

#define T_STEPS 2048
#define NB 32      // batch
#define NI 64      // input dim
#define NM 1024    // M == H
#define NBLK 144
#define NTHR 512

typedef unsigned long long u64;

// ---------------- device storage (static, no allocation) ----------------
__device__ __align__(16) float g_Vm1T[NM*NM];
__device__ __align__(16) float g_Vm2T[NM*NM];
__device__ __align__(16) float g_Pm2m1T[NM*NM];   // (Wm2@Vm1)^T
__device__ __align__(16) float g_Wh1T[NM*NM];
__device__ __align__(16) float g_Q1T[NM*NM];      // (Wmh1@Vm2)^T
__device__ __align__(16) float g_Q2T[NM*NM];      // (Wmh1@Wm2@Vm1)^T
__device__ __align__(16) float g_Win2T[NM*NM];
__device__ __align__(16) float g_Wh2T[NM*NM];
__device__ __align__(16) float g_Wmh2T[NM*NM];
__device__ __align__(16) float g_Wm1T[NI*NM];
__device__ __align__(16) float g_Pm2xT[NI*NM];    // (Wm2@Wm1)^T
__device__ __align__(16) float g_Win1effT[NI*NM]; // (Win1 + Wmh1@Wm2@Wm1)^T
__device__ __align__(16) float g_xT[T_STEPS*NI*NB];
// h states, layout [n][b], double buffered (m states folded into partials)
__device__ __align__(16) float g_h1T[2][NM*NB];
__device__ __align__(16) float g_h2T[2][NM*NB];
// partial products, [parity][mm][n][b]
__device__ __align__(16) float g_partial[2][9][NM*NB];

// Monotone two-level generation counters (never reset; bases read at start).
__device__ unsigned g_fc1[8]; __device__ unsigned g_fc2; __device__ unsigned g_fgen; // full: 144 = 18/stripe
__device__ unsigned g_mc1[8]; __device__ unsigned g_mc2; __device__ unsigned g_mgen; // m-partials: 48 = 6/stripe
__device__ unsigned g_pc1[8]; __device__ unsigned g_pc2; __device__ unsigned g_pgen; // h-partials: 96 = 12/stripe
__device__ unsigned g_hc1[8]; __device__ unsigned g_hc2; __device__ unsigned g_hgen; // h-states: 64 = 8/stripe

#define FMA2(acc, a, b) asm("fma.rn.f32x2 %0, %1, %2, %0;" : "+l"(acc) : "l"(a), "l"(b))
#define ADD2(acc, b)    asm("add.rn.f32x2 %0, %0, %1;"     : "+l"(acc) : "l"(b))
#define PACK2(w2, wu)   asm("mov.b64 %0, {%1, %1};"        : "=l"(w2)  : "r"(wu))

__device__ __forceinline__ unsigned ld_acq(const unsigned* p) {
    unsigned v;
    asm volatile("ld.global.acquire.gpu.u32 %0, [%1];" : "=r"(v) : "l"(p) : "memory");
    return v;
}

// ---------------- setup (3 launches total before persist) ----------------

// launch 0: all transposes + x transpose + h-state zero. grid (4096, 9)
__global__ void fused_setup_kernel(const float* __restrict__ x,
                                   const float* __restrict__ Vm1, const float* __restrict__ Vm2,
                                   const float* __restrict__ Wh1, const float* __restrict__ Win2,
                                   const float* __restrict__ Wh2, const float* __restrict__ Wmh2,
                                   const float* __restrict__ Wm1) {
    const int y = blockIdx.y;
    int idx = blockIdx.x * 256 + threadIdx.x;
    if (y < 6) {
        const float* in; float* out;
        switch (y) {
            case 0: in = Vm1;  out = g_Vm1T;  break;
            case 1: in = Vm2;  out = g_Vm2T;  break;
            case 2: in = Wh1;  out = g_Wh1T;  break;
            case 3: in = Win2; out = g_Win2T; break;
            case 4: in = Wh2;  out = g_Wh2T;  break;
            default:in = Wmh2; out = g_Wmh2T; break;
        }
        int r = idx >> 10, c = idx & 1023;
        out[(size_t)c * NM + r] = in[idx];
    } else if (y == 6) {
        if (idx < NM * NI) {
            int r = idx / NI, c = idx % NI;
            g_Wm1T[(size_t)c * NM + r] = Wm1[idx];
        }
    } else if (y == 7) {
        for (int i = idx; i < NB * T_STEPS * NI; i += 4096 * 256) {
            int b = i >> 17;
            int r = i & 131071;
            int tt = r >> 6;
            int ii = r & 63;
            g_xT[tt * (NI * NB) + ii * NB + b] = x[i];
        }
    } else {
        if (idx < 65536) {
            ((float*)g_h1T)[idx] = 0.f;
            ((float*)g_h2T)[idx] = 0.f;
        }
    }
}

__device__ __forceinline__ void gemm_pre_body(const float* __restrict__ X, const float* __restrict__ Y,
                                              const float* __restrict__ Cm, float* __restrict__ out,
                                              int N, int J, int K, int transY, int addC) {
    __shared__ float As[64][17];
    __shared__ float Bs[16][68];
    int tx = threadIdx.x, ty = threadIdx.y;
    int tid = ty * 16 + tx;
    int n0 = blockIdx.x * 64, k0 = blockIdx.y * 64;
    float c[4][4];
    #pragma unroll
    for (int i = 0; i < 4; i++)
        #pragma unroll
        for (int l = 0; l < 4; l++) c[i][l] = 0.f;

    for (int jt = 0; jt < J; jt += 16) {
        for (int e = tid; e < 1024; e += 256) {
            int r = e >> 4, cc = e & 15;
            As[r][cc] = transY ? Y[(size_t)(k0 + r) * J + jt + cc]
                               : Y[(size_t)(jt + cc) * K + k0 + r];
        }
        for (int e = tid; e < 1024; e += 256) {
            int jj = e >> 6, nn = e & 63;
            Bs[jj][nn] = X[(size_t)(n0 + nn) * J + jt + jj];
        }
        __syncthreads();
        #pragma unroll
        for (int j = 0; j < 16; j++) {
            float a[4], b[4];
            #pragma unroll
            for (int i = 0; i < 4; i++) a[i] = As[ty * 4 + i][j];
            #pragma unroll
            for (int i = 0; i < 4; i++) b[i] = Bs[j][tx * 4 + i];
            #pragma unroll
            for (int i = 0; i < 4; i++)
                #pragma unroll
                for (int l = 0; l < 4; l++) c[i][l] += a[i] * b[l];
        }
        __syncthreads();
    }
    #pragma unroll
    for (int i = 0; i < 4; i++)
        #pragma unroll
        for (int l = 0; l < 4; l++) {
            int k = k0 + ty * 4 + i, n = n0 + tx * 4 + l;
            float v = c[i][l];
            if (addC) v += Cm[(size_t)n * K + k];
            out[(size_t)k * N + n] = v;
        }
}

// launch 1
__global__ void pre_wave1_kernel(const float* __restrict__ Wm2, const float* __restrict__ Vm1,
                                 const float* __restrict__ Wmh1, const float* __restrict__ Vm2,
                                 const float* __restrict__ Wm1) {
    if (blockIdx.z == 0)      gemm_pre_body(Wm2,  Vm1, nullptr, g_Pm2m1T, NM, NM, NM, 0, 0);
    else if (blockIdx.z == 1) gemm_pre_body(Wmh1, Vm2, nullptr, g_Q1T,    NM, NM, NM, 0, 0);
    else { if (blockIdx.y > 0) return;
           gemm_pre_body(Wm2,  Wm1, nullptr, g_Pm2xT,  NM, NM, NI, 0, 0); }
}

// launch 2
__global__ void pre_wave2_kernel(const float* __restrict__ Wmh1, const float* __restrict__ Win1) {
    if (blockIdx.z == 0)      gemm_pre_body(Wmh1, g_Pm2m1T, nullptr, g_Q2T,     NM, NM, NM, 1, 0);
    else { if (blockIdx.y > 0) return;
           gemm_pre_body(Wmh1, g_Pm2xT, Win1, g_Win1effT, NM, NM, NI, 1, 1); }
}

// ---------------- persistent kernel ----------------
// 144 blocks x 512 threads (1 CTA/SM). Block = (mm, 64-col slice).
// Producer/consumer generation counters; the full barrier only guards the
// partial-buffer WAR and its wait is hidden inside the reduction.

__device__ __forceinline__ void ctr_arrive(unsigned* c1, unsigned* c2, unsigned* gen,
                                           unsigned target, unsigned perStripe) {
    // caller must have __syncthreads()'d; tid0 only
    if (threadIdx.x == 0) {
        __threadfence();
        unsigned s = atomicAdd(&c1[blockIdx.x & 7], 1) + 1;
        if (s == target * perStripe) {
            unsigned t2 = atomicAdd(c2, 1) + 1;
            if (t2 == target * 8u) {
                __threadfence();
                *gen = target;
            }
        }
    }
}
__device__ __forceinline__ void ctr_wait(const unsigned* gen, unsigned target) {
    if (threadIdx.x == 0) {
        while (ld_acq(gen) < target) { }
    }
    __syncthreads();
}

// one k-step: 1 pack + 8 broadcast LDS.128 + 32 FFMA2 into acc[0..31]
__device__ __forceinline__ void fma_step(u64* acc, const float* saRow, float2 wv) {
    uint32_t wxu = __float_as_uint(wv.x), wyu = __float_as_uint(wv.y);
    u64 wa, wb;
    PACK2(wa, wxu);
    PACK2(wb, wyu);
    const ulonglong2* ap = (const ulonglong2*)saRow;
    #pragma unroll
    for (int h = 0; h < 2; h++) {
        ulonglong2 q0 = ap[h*4+0], q1 = ap[h*4+1], q2 = ap[h*4+2], q3 = ap[h*4+3];
        int o = h * 8;
        FMA2(acc[o+0], wa, q0.x); FMA2(acc[16+o+0], wb, q0.x);
        FMA2(acc[o+1], wa, q0.y); FMA2(acc[16+o+1], wb, q0.y);
        FMA2(acc[o+2], wa, q1.x); FMA2(acc[16+o+2], wb, q1.x);
        FMA2(acc[o+3], wa, q1.y); FMA2(acc[16+o+3], wb, q1.y);
        FMA2(acc[o+4], wa, q2.x); FMA2(acc[16+o+4], wb, q2.x);
        FMA2(acc[o+5], wa, q2.y); FMA2(acc[16+o+5], wb, q2.y);
        FMA2(acc[o+6], wa, q3.x); FMA2(acc[16+o+6], wb, q3.x);
        FMA2(acc[o+7], wa, q3.y); FMA2(acc[16+o+7], wb, q3.y);
    }
}

extern "C" __global__ void __launch_bounds__(NTHR, 1)
persist_kernel(const float* __restrict__ b1, const float* __restrict__ b2,
               float* __restrict__ out) {
    extern __shared__ float sA[];           // 128 KB A + 8 KB sX
    float* sX = sA + NM * NB;
    __shared__ float tile[32 * 33];
    __shared__ unsigned s_bF, s_bM, s_bP, s_bH;

    const int tid  = threadIdx.x;
    const int w    = tid >> 5, lane = tid & 31;
    const int kq   = w;                     // 0..15
    const int bx   = blockIdx.x;
    const int mm   = bx >> 4;
    const int blk  = bx & 15;

    // combiner roles: bx 0-31 -> h1 tiles; bx 32-47 & 64-79 -> h2 tiles
    int  kindH = 0, ctile = 0;
    if (bx < 32)                 { kindH = 1; ctile = bx; }
    else if (bx < 48)            { kindH = 2; ctile = bx - 32; }
    else if (bx >= 64 && bx < 80){ kindH = 2; ctile = bx - 48; }

    const float *W, *Wx = 0;
    switch (mm) {
        case 0: W = g_Vm1T;   Wx = g_Wm1T;     break;
        case 1: W = g_Vm2T;   Wx = g_Pm2xT;    break;
        case 2: W = g_Pm2m1T;                  break;
        case 3: W = g_Wh1T;   Wx = g_Win1effT; break;
        case 4: W = g_Q1T;                     break;
        case 5: W = g_Q2T;                     break;
        case 6: W = g_Win2T;                   break;
        case 7: W = g_Wh2T;                    break;
        default:W = g_Wmh2T;                   break;
    }
    const bool isM1src = (mm == 0) || (mm == 2) || (mm == 5);   // A = m1 = p0
    const bool isM2src = (mm == 1) || (mm == 4) || (mm == 8);   // A = m2 = p1+p2

    if (tid == 0) { s_bF = g_fgen; s_bM = g_mgen; s_bP = g_pgen; s_bH = g_hgen; }
    __syncthreads();
    const unsigned bF = s_bF, bM = s_bM, bP = s_bP, bH = s_bH;

    for (int t = 0; t <= T_STEPS; t++) {
        const int cur  = t & 1;
        const int parW = t & 1;            // partials written this step
        const int parR = (t - 1) & 1;      // partials from previous step

        u64 acc[32];
        #pragma unroll
        for (int i = 0; i < 32; i++) acc[i] = 0ull;

        // ---- per-warp x phase (mm 0,1,3): independent of all gates ----
        if (Wx) {
            int tt = t < T_STEPS ? t : T_STEPS - 1;
            ((float4*)sX)[w * 32 + lane] =
                ((const float4*)(g_xT + (size_t)tt * (NI * NB)))[w * 32 + lane];
            __syncwarp();
            const float2* xp = (const float2*)Wx + blk * 32 + lane;
            #pragma unroll
            for (int u = 0; u < 4; u++) {
                int kk = kq * 4 + u;
                float2 wv = __ldg(xp + (size_t)kk * 512);
                fma_step(acc, sX + kk * 32, wv);
            }
        }

        // ---- gate + per-warp A slice stage: rows [64*kq, 64*kq+64) ----
        {
            float4* d4 = (float4*)sA;
            const int io = w * 512 + lane;
            if (t == 0) {
                float4 z = make_float4(0.f, 0.f, 0.f, 0.f);
                #pragma unroll
                for (int i = 0; i < 16; i++) d4[io + i * 32] = z;
            } else if (isM1src) {
                ctr_wait(&g_mgen, bM + (unsigned)t);
                const float4* s4 = (const float4*)g_partial[parR][0];
                #pragma unroll
                for (int i = 0; i < 16; i++) d4[io + i * 32] = s4[io + i * 32];
            } else if (isM2src) {
                ctr_wait(&g_mgen, bM + (unsigned)t);
                const float4* s1 = (const float4*)g_partial[parR][1];
                const float4* s2 = (const float4*)g_partial[parR][2];
                #pragma unroll
                for (int i = 0; i < 16; i++) {
                    float4 a = s1[io + i * 32], b = s2[io + i * 32];
                    d4[io + i * 32] = make_float4(a.x + b.x, a.y + b.y, a.z + b.z, a.w + b.w);
                }
            } else {
                ctr_wait(&g_hgen, bH + (unsigned)t);   // combine(t-1) done
                const float4* s4 = (const float4*)((mm == 7) ? g_h2T[cur] : g_h1T[cur]);
                #pragma unroll
                for (int i = 0; i < 16; i++) d4[io + i * 32] = s4[io + i * 32];
            }
        }
        __syncwarp();

        // ---- main 64-k loop, depth-4 weight prefetch (LDG.64) ----
        {
            const float2* wp2 = (const float2*)W + (size_t)(kq * 64) * 512 + blk * 32 + lane;
            const float*  saw = sA + (kq * 64) * 32;
            float2 pf[4];
            #pragma unroll
            for (int u = 0; u < 4; u++) pf[u] = __ldg(wp2 + (size_t)u * 512);
            for (int kc = 0; kc < 64; kc += 4) {
                #pragma unroll
                for (int u = 0; u < 4; u++) {
                    float2 wv = pf[u];
                    pf[u] = __ldg(wp2 + (size_t)(((kc + 4 + u) & 63)) * 512);
                    fma_step(acc, saw + (kc + u) * 32, wv);
                }
            }
        }

        // ---- cross-kq reduction; full-gen WAR wait fused with the mid-sync ----
        u64* Rsm = (u64*)sA;
        {
            int base = (w * 32 + lane) * 32;
            #pragma unroll
            for (int a = 0; a < 32; a++)
                Rsm[base + ((a + lane) & 31)] = acc[a];
        }
        if (t > 0) ctr_wait(&g_fgen, bF + (unsigned)t);   // hidden in steady state
        else       __syncthreads();
        {
            u64* pout = (u64*)(g_partial[parW][mm]) + (size_t)blk * 1024;
            #pragma unroll
            for (int r = 0; r < 2; r++) {
                int o  = tid * 2 + r;
                int nl = o >> 4, bp = o & 15;
                int ls = nl >> 1;
                int a  = ((nl & 1) << 4) + bp;
                int idx = ls * 32 + ((a + ls) & 31);
                u64 v[16];
                #pragma unroll
                for (int q = 0; q < 16; q++) v[q] = Rsm[q * 1024 + idx];
                #pragma unroll
                for (int st = 8; st >= 1; st >>= 1)
                    #pragma unroll
                    for (int q = 0; q < 8; q++)
                        if (q < st) ADD2(v[q], v[q + st]);
                pout[o] = v[0];
            }
        }
        __syncthreads();

        // ---- arrivals: full always; role counter per producer group ----
        ctr_arrive(g_fc1, &g_fc2, &g_fgen, bF + (unsigned)(t + 1), 18u);
        if (mm < 3) ctr_arrive(g_mc1, &g_mc2, &g_mgen, bM + (unsigned)(t + 1), 6u);
        else        ctr_arrive(g_pc1, &g_pc2, &g_pgen, bP + (unsigned)(t + 1), 12u);

        // ---- h combine (64 combiner blocks), gated on h-partials only ----
        if (kindH) {
            ctr_wait(&g_pgen, bP + (unsigned)(t + 1));
            const int n0c = ctile * 32;
            const int nxt = cur ^ 1;
            if (kindH == 1) {
                const float* p3 = g_partial[parW][3];
                const float* p4 = g_partial[parW][4];
                const float* p5 = g_partial[parW][5];
                if (tid < 256) {
                    int cw = tid >> 5, cl = tid & 31;
                    #pragma unroll
                    for (int rr = 0; rr < 4; rr++) {
                        int nn = n0c + cw * 4 + rr;
                        int off = nn * NB + cl;
                        float v = tanhf(p3[off] + p4[off] + p5[off] + b1[nn]);
                        g_h1T[nxt][off] = 0.5f * g_h1T[cur][off] + 0.5f * v;
                    }
                }
            } else {
                const float* p6 = g_partial[parW][6];
                const float* p7 = g_partial[parW][7];
                const float* p8 = g_partial[parW][8];
                if (tid < 256) {
                    int cw = tid >> 5, cl = tid & 31;
                    #pragma unroll
                    for (int rr = 0; rr < 4; rr++) {
                        int nn = n0c + cw * 4 + rr;
                        int off = nn * NB + cl;
                        float v = tanhf(p6[off] + p7[off] + p8[off] + b2[nn]);
                        if (t >= 1) {
                            float h2v = 0.5f * g_h2T[cur][off] + 0.5f * v;
                            g_h2T[nxt][off] = h2v;
                            tile[(nn - n0c) * 33 + cl] = h2v;
                        }
                    }
                }
                if (t >= 1) {
                    __syncthreads();
                    if (tid < 256) {
                        int cw = tid >> 5, cl = tid & 31;
                        #pragma unroll
                        for (int rr = 0; rr < 4; rr++) {
                            int b = cw * 4 + rr;
                            out[(size_t)b * T_STEPS * NM + (size_t)(t - 1) * NM + n0c + cl] =
                                tile[cl * 33 + b];
                        }
                    }
                }
            }
            __syncthreads();
            ctr_arrive(g_hc1, &g_hc2, &g_hgen, bH + (unsigned)(t + 1), 8u);
        }
    }
}

// ---------------- launch ----------------
extern "C" void kernel_launch(void* const* d_in, const int* in_sizes, int n_in,
                              void* d_out, int out_size) {
    const float* x    = (const float*)d_in[0];
    const float* Wm1  = (const float*)d_in[1];
    const float* Vm1  = (const float*)d_in[2];
    const float* Wm2  = (const float*)d_in[3];
    const float* Vm2  = (const float*)d_in[4];
    const float* Win1 = (const float*)d_in[5];
    const float* Wh1  = (const float*)d_in[6];
    const float* Wmh1 = (const float*)d_in[7];
    const float* b1   = (const float*)d_in[8];
    const float* Win2 = (const float*)d_in[9];
    const float* Wh2  = (const float*)d_in[10];
    const float* Wmh2 = (const float*)d_in[11];
    const float* b2   = (const float*)d_in[12];
    float* out = (float*)d_out;

    // 3 setup launches, then persist (lands on the ncu -s 5 capture slot)
    fused_setup_kernel<<<dim3(4096, 9), 256>>>(x, Vm1, Vm2, Wh1, Win2, Wh2, Wmh2, Wm1);
    pre_wave1_kernel<<<dim3(16, 16, 3), dim3(16, 16)>>>(Wm2, Vm1, Wmh1, Vm2, Wm1);
    pre_wave2_kernel<<<dim3(16, 16, 2), dim3(16, 16)>>>(Wmh1, Win1);

    const int SMEM = (NM * NB + NI * NB) * 4;   // 136 KB
    cudaFuncSetAttribute(persist_kernel,
                         cudaFuncAttributeMaxDynamicSharedMemorySize, SMEM);
    persist_kernel<<<NBLK, NTHR, SMEM>>>(b1, b2, out);
}

// round 17
// speedup vs baseline: 1.7125x; 1.7125x over previous
#include <cuda_runtime.h>
#include <cstdint>

#define T_STEPS 2048
#define NB 32      // batch
#define NI 64      // input dim
#define NM 1024    // M == H
#define NBLK 144
#define NTHR 512

typedef unsigned long long u64;

// ---------------- device storage (static, no allocation) ----------------
__device__ __align__(16) float g_Vm1T[NM*NM];
__device__ __align__(16) float g_Vm2T[NM*NM];
__device__ __align__(16) float g_Pm2m1T[NM*NM];   // (Wm2@Vm1)^T
__device__ __align__(16) float g_Wh1T[NM*NM];
__device__ __align__(16) float g_Q1T[NM*NM];      // (Wmh1@Vm2)^T
__device__ __align__(16) float g_Q2T[NM*NM];      // (Wmh1@Wm2@Vm1)^T
__device__ __align__(16) float g_Win2T[NM*NM];
__device__ __align__(16) float g_Wh2T[NM*NM];
__device__ __align__(16) float g_Wmh2T[NM*NM];
__device__ __align__(16) float g_Wm1T[NI*NM];
__device__ __align__(16) float g_Pm2xT[NI*NM];    // (Wm2@Wm1)^T
__device__ __align__(16) float g_Win1effT[NI*NM]; // (Win1 + Wmh1@Wm2@Wm1)^T
__device__ __align__(16) float g_xT[T_STEPS*NI*NB];
// h states, layout [n][b], double buffered (m states are folded into partials)
__device__ __align__(16) float g_h1T[2][NM*NB];
__device__ __align__(16) float g_h2T[2][NM*NB];
// partial products, [parity][mm][n][b]
__device__ __align__(16) float g_partial[2][9][NM*NB];

// global barrier (two-level, striped arrive + single-word detect), MONOTONE
__device__ unsigned g_cnt1[8];
__device__ unsigned g_cnt2;
__device__ unsigned g_gen;
// h-combine-done counter (same pattern, 64 arrivals = 8 stripes x 8), MONOTONE
__device__ unsigned g_hcnt1[8];
__device__ unsigned g_hcnt2;
__device__ unsigned g_hgen;

#define FMA2(acc, a, b) asm("fma.rn.f32x2 %0, %1, %2, %0;" : "+l"(acc) : "l"(a), "l"(b))
#define ADD2(acc, b)    asm("add.rn.f32x2 %0, %0, %1;"     : "+l"(acc) : "l"(b))
#define PACK2(w2, wu)   asm("mov.b64 %0, {%1, %1};"        : "=l"(w2)  : "r"(wu))

__device__ __forceinline__ unsigned ld_acq(const unsigned* p) {
    unsigned v;
    asm volatile("ld.global.acquire.gpu.u32 %0, [%1];" : "=r"(v) : "l"(p) : "memory");
    return v;
}

// ---------------- setup (3 launches total before persist) ----------------

// launch 0: all transposes + x transpose + h-state zero. grid (4096, 9)
__global__ void fused_setup_kernel(const float* __restrict__ x,
                                   const float* __restrict__ Vm1, const float* __restrict__ Vm2,
                                   const float* __restrict__ Wh1, const float* __restrict__ Win2,
                                   const float* __restrict__ Wh2, const float* __restrict__ Wmh2,
                                   const float* __restrict__ Wm1) {
    const int y = blockIdx.y;
    int idx = blockIdx.x * 256 + threadIdx.x;
    if (y < 6) {                                // 6 big transposes [NM,NM]
        const float* in; float* out;
        switch (y) {
            case 0: in = Vm1;  out = g_Vm1T;  break;
            case 1: in = Vm2;  out = g_Vm2T;  break;
            case 2: in = Wh1;  out = g_Wh1T;  break;
            case 3: in = Win2; out = g_Win2T; break;
            case 4: in = Wh2;  out = g_Wh2T;  break;
            default:in = Wmh2; out = g_Wmh2T; break;
        }
        int r = idx >> 10, c = idx & 1023;
        out[(size_t)c * NM + r] = in[idx];
    } else if (y == 6) {                        // Wm1 transpose [NM,NI]
        if (idx < NM * NI) {
            int r = idx / NI, c = idx % NI;
            g_Wm1T[(size_t)c * NM + r] = Wm1[idx];
        }
    } else if (y == 7) {                        // x[b][t][i] -> g_xT[t][i][b]
        for (int i = idx; i < NB * T_STEPS * NI; i += 4096 * 256) {
            int b = i >> 17;
            int r = i & 131071;
            int tt = r >> 6;
            int ii = r & 63;
            g_xT[tt * (NI * NB) + ii * NB + b] = x[i];
        }
    } else {                                    // zero h states (in-graph reset)
        if (idx < 65536) {
            ((float*)g_h1T)[idx] = 0.f;
            ((float*)g_h2T)[idx] = 0.f;
        }
    }
}

__device__ __forceinline__ void gemm_pre_body(const float* __restrict__ X, const float* __restrict__ Y,
                                              const float* __restrict__ Cm, float* __restrict__ out,
                                              int N, int J, int K, int transY, int addC) {
    __shared__ float As[64][17];
    __shared__ float Bs[16][68];
    int tx = threadIdx.x, ty = threadIdx.y;
    int tid = ty * 16 + tx;
    int n0 = blockIdx.x * 64, k0 = blockIdx.y * 64;
    float c[4][4];
    #pragma unroll
    for (int i = 0; i < 4; i++)
        #pragma unroll
        for (int l = 0; l < 4; l++) c[i][l] = 0.f;

    for (int jt = 0; jt < J; jt += 16) {
        for (int e = tid; e < 1024; e += 256) {
            int r = e >> 4, cc = e & 15;
            As[r][cc] = transY ? Y[(size_t)(k0 + r) * J + jt + cc]
                               : Y[(size_t)(jt + cc) * K + k0 + r];
        }
        for (int e = tid; e < 1024; e += 256) {
            int jj = e >> 6, nn = e & 63;
            Bs[jj][nn] = X[(size_t)(n0 + nn) * J + jt + jj];
        }
        __syncthreads();
        #pragma unroll
        for (int j = 0; j < 16; j++) {
            float a[4], b[4];
            #pragma unroll
            for (int i = 0; i < 4; i++) a[i] = As[ty * 4 + i][j];
            #pragma unroll
            for (int i = 0; i < 4; i++) b[i] = Bs[j][tx * 4 + i];
            #pragma unroll
            for (int i = 0; i < 4; i++)
                #pragma unroll
                for (int l = 0; l < 4; l++) c[i][l] += a[i] * b[l];
        }
        __syncthreads();
    }
    #pragma unroll
    for (int i = 0; i < 4; i++)
        #pragma unroll
        for (int l = 0; l < 4; l++) {
            int k = k0 + ty * 4 + i, n = n0 + tx * 4 + l;
            float v = c[i][l];
            if (addC) v += Cm[(size_t)n * K + k];
            out[(size_t)k * N + n] = v;
        }
}

// launch 1
__global__ void pre_wave1_kernel(const float* __restrict__ Wm2, const float* __restrict__ Vm1,
                                 const float* __restrict__ Wmh1, const float* __restrict__ Vm2,
                                 const float* __restrict__ Wm1) {
    if (blockIdx.z == 0)      gemm_pre_body(Wm2,  Vm1, nullptr, g_Pm2m1T, NM, NM, NM, 0, 0);
    else if (blockIdx.z == 1) gemm_pre_body(Wmh1, Vm2, nullptr, g_Q1T,    NM, NM, NM, 0, 0);
    else { if (blockIdx.y > 0) return;
           gemm_pre_body(Wm2,  Wm1, nullptr, g_Pm2xT,  NM, NM, NI, 0, 0); }
}

// launch 2
__global__ void pre_wave2_kernel(const float* __restrict__ Wmh1, const float* __restrict__ Win1) {
    if (blockIdx.z == 0)      gemm_pre_body(Wmh1, g_Pm2m1T, nullptr, g_Q2T,     NM, NM, NM, 1, 0);
    else { if (blockIdx.y > 0) return;
           gemm_pre_body(Wmh1, g_Pm2xT, Win1, g_Win1effT, NM, NM, NI, 1, 1); }
}

// ---------------- persistent kernel ----------------
// 144 blocks x 512 threads (1 CTA/SM). Block = (mm, 64-col slice).
// 16 warps = 16 kq (64 k each). Warp: 64 n x 32 b = 32 f32x2 accumulators.
// Single global barrier per step. m-states folded into partial reads.
// h-states produced post-barrier by 64 m-role combiner blocks, gated by g_hgen.

__device__ __forceinline__ void grid_sync(unsigned target) {
    __syncthreads();
    if (threadIdx.x == 0) {
        __threadfence();
        unsigned s = atomicAdd(&g_cnt1[blockIdx.x & 7], 1) + 1;
        if (s == target * 18u) {
            unsigned t2 = atomicAdd(&g_cnt2, 1) + 1;
            if (t2 == target * 8u) {
                __threadfence();
                g_gen = target;
            }
        }
        while (ld_acq(&g_gen) < target) { }
    }
    __syncthreads();
}

__device__ __forceinline__ void hgen_arrive(unsigned target) {
    __syncthreads();                     // combine writes done block-wide
    if (threadIdx.x == 0) {
        __threadfence();
        unsigned s = atomicAdd(&g_hcnt1[blockIdx.x & 7], 1) + 1;
        if (s == target * 8u) {
            unsigned t2 = atomicAdd(&g_hcnt2, 1) + 1;
            if (t2 == target * 8u) {
                __threadfence();
                g_hgen = target;
            }
        }
    }
}

__device__ __forceinline__ void hgen_wait(unsigned target) {
    if (threadIdx.x == 0) {
        while (ld_acq(&g_hgen) < target) { }
    }
    __syncthreads();
}

// one k-step: 1 pack + 8 broadcast LDS.128 + 32 FFMA2 into acc[0..31]
__device__ __forceinline__ void fma_step(u64* acc, const float* saRow, float2 wv) {
    uint32_t wxu = __float_as_uint(wv.x), wyu = __float_as_uint(wv.y);
    u64 wa, wb;
    PACK2(wa, wxu);
    PACK2(wb, wyu);
    const ulonglong2* ap = (const ulonglong2*)saRow;
    #pragma unroll
    for (int h = 0; h < 2; h++) {
        ulonglong2 q0 = ap[h*4+0], q1 = ap[h*4+1], q2 = ap[h*4+2], q3 = ap[h*4+3];
        int o = h * 8;
        FMA2(acc[o+0], wa, q0.x); FMA2(acc[16+o+0], wb, q0.x);
        FMA2(acc[o+1], wa, q0.y); FMA2(acc[16+o+1], wb, q0.y);
        FMA2(acc[o+2], wa, q1.x); FMA2(acc[16+o+2], wb, q1.x);
        FMA2(acc[o+3], wa, q1.y); FMA2(acc[16+o+3], wb, q1.y);
        FMA2(acc[o+4], wa, q2.x); FMA2(acc[16+o+4], wb, q2.x);
        FMA2(acc[o+5], wa, q2.y); FMA2(acc[16+o+5], wb, q2.y);
        FMA2(acc[o+6], wa, q3.x); FMA2(acc[16+o+6], wb, q3.x);
        FMA2(acc[o+7], wa, q3.y); FMA2(acc[16+o+7], wb, q3.y);
    }
}

extern "C" __global__ void __launch_bounds__(NTHR, 1)
persist_kernel(const float* __restrict__ b1, const float* __restrict__ b2,
               float* __restrict__ out) {
    extern __shared__ float sA[];           // 128 KB A + 8 KB sX
    float* sX = sA + NM * NB;
    __shared__ float tile[32 * 33];
    __shared__ unsigned s_base, s_baseh;

    const int tid  = threadIdx.x;
    const int w    = tid >> 5, lane = tid & 31;
    const int kq   = w;                     // 0..15
    const int bx   = blockIdx.x;
    const int mm   = bx >> 4;
    const int blk  = bx & 15;

    // combiner role mapping: bx 0-31 -> h1 tiles 0-31; bx 32-47 & 64-79 -> h2 tiles 0-31
    int  kindH = 0, ctile = 0;
    if (bx < 32)                { kindH = 1; ctile = bx; }
    else if (bx < 48)           { kindH = 2; ctile = bx - 32; }
    else if (bx >= 64 && bx < 80){ kindH = 2; ctile = bx - 48; }

    const float *W, *Wx = 0;
    switch (mm) {
        case 0: W = g_Vm1T;   Wx = g_Wm1T;     break;
        case 1: W = g_Vm2T;   Wx = g_Pm2xT;    break;
        case 2: W = g_Pm2m1T;                  break;
        case 3: W = g_Wh1T;   Wx = g_Win1effT; break;
        case 4: W = g_Q1T;                     break;
        case 5: W = g_Q2T;                     break;
        case 6: W = g_Win2T;                   break;
        case 7: W = g_Wh2T;                    break;
        default:W = g_Wmh2T;                   break;
    }
    const bool isM1src = (mm == 0) || (mm == 2) || (mm == 5);   // A = m1 = p0
    const bool isM2src = (mm == 1) || (mm == 4) || (mm == 8);   // A = m2 = p1+p2

    if (tid == 0) { s_base = g_gen; s_baseh = g_hgen; }
    __syncthreads();
    unsigned bar = s_base;
    const unsigned baseh = s_baseh;

    for (int t = 0; t <= T_STEPS; t++) {
        const int cur  = t & 1;
        const int parW = t & 1;            // partials written this step
        const int parR = (t - 1) & 1;      // partials from previous step
        const bool runMain = (t < T_STEPS) || (mm >= 6);

        if (runMain) {
            u64 acc[32];
            #pragma unroll
            for (int i = 0; i < 32; i++) acc[i] = 0ull;

            // ---- per-warp x phase (mm 0,1,3): independent of states ----
            if (Wx) {
                int tt = t < T_STEPS ? t : T_STEPS - 1;
                ((float4*)sX)[w * 32 + lane] =
                    ((const float4*)(g_xT + (size_t)tt * (NI * NB)))[w * 32 + lane];
                __syncwarp();
                const float2* xp = (const float2*)Wx + blk * 32 + lane;
                #pragma unroll
                for (int u = 0; u < 4; u++) {
                    int kk = kq * 4 + u;
                    float2 wv = __ldg(xp + (size_t)kk * 512);
                    fma_step(acc, sX + kk * 32, wv);
                }
            }

            // ---- per-warp A slice stage: rows [64*kq, 64*kq+64) ----
            {
                float4* d4 = (float4*)sA;
                const int io = w * 512 + lane;
                if (t == 0) {
                    float4 z = make_float4(0.f, 0.f, 0.f, 0.f);
                    #pragma unroll
                    for (int i = 0; i < 16; i++) d4[io + i * 32] = z;
                } else if (isM1src) {
                    const float4* s4 = (const float4*)g_partial[parR][0];
                    #pragma unroll
                    for (int i = 0; i < 16; i++) d4[io + i * 32] = s4[io + i * 32];
                } else if (isM2src) {
                    const float4* s1 = (const float4*)g_partial[parR][1];
                    const float4* s2 = (const float4*)g_partial[parR][2];
                    #pragma unroll
                    for (int i = 0; i < 16; i++) {
                        float4 a = s1[io + i * 32], b = s2[io + i * 32];
                        d4[io + i * 32] = make_float4(a.x + b.x, a.y + b.y, a.z + b.z, a.w + b.w);
                    }
                } else {
                    hgen_wait(baseh + (unsigned)t);    // combine(t-1) done
                    const float4* s4 = (const float4*)((mm == 7) ? g_h2T[cur] : g_h1T[cur]);
                    #pragma unroll
                    for (int i = 0; i < 16; i++) d4[io + i * 32] = s4[io + i * 32];
                }
            }
            __syncwarp();

            // ---- main 64-k loop, depth-4 weight prefetch (LDG.64) ----
            {
                const float2* wp2 = (const float2*)W + (size_t)(kq * 64) * 512 + blk * 32 + lane;
                const float*  saw = sA + (kq * 64) * 32;
                float2 pf[4];
                #pragma unroll
                for (int u = 0; u < 4; u++) pf[u] = __ldg(wp2 + (size_t)u * 512);
                for (int kc = 0; kc < 64; kc += 4) {
                    #pragma unroll
                    for (int u = 0; u < 4; u++) {
                        float2 wv = pf[u];
                        pf[u] = __ldg(wp2 + (size_t)(((kc + 4 + u) & 63)) * 512);
                        fma_step(acc, saw + (kc + u) * 32, wv);
                    }
                }
            }

            // ---- cross-kq reduction (warp-region-local scratch) ----
            u64* Rsm = (u64*)sA;
            {
                int base = (w * 32 + lane) * 32;
                #pragma unroll
                for (int a = 0; a < 32; a++)
                    Rsm[base + ((a + lane) & 31)] = acc[a];
            }
            __syncthreads();
            {
                u64* pout = (u64*)(g_partial[parW][mm]) + (size_t)blk * 1024;
                #pragma unroll
                for (int r = 0; r < 2; r++) {
                    int o  = tid * 2 + r;
                    int nl = o >> 4, bp = o & 15;
                    int ls = nl >> 1;
                    int a  = ((nl & 1) << 4) + bp;
                    int idx = ls * 32 + ((a + ls) & 31);
                    u64 v[16];
                    #pragma unroll
                    for (int q = 0; q < 16; q++) v[q] = Rsm[q * 1024 + idx];
                    #pragma unroll
                    for (int st = 8; st >= 1; st >>= 1)
                        #pragma unroll
                        for (int q = 0; q < 8; q++)
                            if (q < st) ADD2(v[q], v[q + st]);
                    pout[o] = v[0];
                }
            }
        }

        // ---- single global barrier per step ----
        grid_sync(++bar);

        // ---- h combine (64 m-role blocks, ALL 512 threads), then signal g_hgen ----
        if (kindH) {
            const int n0c = ctile * 32;
            const int nxt = cur ^ 1;
            const int cw = tid >> 5, cl = tid & 31;   // 16 warps x 2 rows each
            if (kindH == 1) {
                const float* p3 = g_partial[parW][3];
                const float* p4 = g_partial[parW][4];
                const float* p5 = g_partial[parW][5];
                #pragma unroll
                for (int rr = 0; rr < 2; rr++) {
                    int nn = n0c + cw * 2 + rr;
                    int off = nn * NB + cl;
                    float v = tanhf(p3[off] + p4[off] + p5[off] + b1[nn]);
                    g_h1T[nxt][off] = 0.5f * g_h1T[cur][off] + 0.5f * v;
                }
                hgen_arrive(baseh + (unsigned)(t + 1));
            } else {
                const float* p6 = g_partial[parW][6];
                const float* p7 = g_partial[parW][7];
                const float* p8 = g_partial[parW][8];
                #pragma unroll
                for (int rr = 0; rr < 2; rr++) {
                    int nn = n0c + cw * 2 + rr;
                    int off = nn * NB + cl;
                    float v = tanhf(p6[off] + p7[off] + p8[off] + b2[nn]);
                    if (t >= 1) {
                        float h2v = 0.5f * g_h2T[cur][off] + 0.5f * v;
                        g_h2T[nxt][off] = h2v;
                        tile[(nn - n0c) * 33 + cl] = h2v;
                    }
                }
                // signal FIRST (h2T written); out-store is off the critical path.
                // hgen_arrive's internal __syncthreads also makes tile visible.
                hgen_arrive(baseh + (unsigned)(t + 1));
                if (t >= 1) {
                    #pragma unroll
                    for (int rr = 0; rr < 2; rr++) {
                        int b = cw * 2 + rr;
                        out[(size_t)b * T_STEPS * NM + (size_t)(t - 1) * NM + n0c + cl] =
                            tile[cl * 33 + b];
                    }
                }
            }
        }
    }
}

// ---------------- launch ----------------
extern "C" void kernel_launch(void* const* d_in, const int* in_sizes, int n_in,
                              void* d_out, int out_size) {
    const float* x    = (const float*)d_in[0];
    const float* Wm1  = (const float*)d_in[1];
    const float* Vm1  = (const float*)d_in[2];
    const float* Wm2  = (const float*)d_in[3];
    const float* Vm2  = (const float*)d_in[4];
    const float* Win1 = (const float*)d_in[5];
    const float* Wh1  = (const float*)d_in[6];
    const float* Wmh1 = (const float*)d_in[7];
    const float* b1   = (const float*)d_in[8];
    const float* Win2 = (const float*)d_in[9];
    const float* Wh2  = (const float*)d_in[10];
    const float* Wmh2 = (const float*)d_in[11];
    const float* b2   = (const float*)d_in[12];
    float* out = (float*)d_out;

    // 3 setup launches, then persist (lands on the ncu -s 5 capture slot)
    fused_setup_kernel<<<dim3(4096, 9), 256>>>(x, Vm1, Vm2, Wh1, Win2, Wh2, Wmh2, Wm1);
    pre_wave1_kernel<<<dim3(16, 16, 3), dim3(16, 16)>>>(Wm2, Vm1, Wmh1, Vm2, Wm1);
    pre_wave2_kernel<<<dim3(16, 16, 2), dim3(16, 16)>>>(Wmh1, Win1);

    const int SMEM = (NM * NB + NI * NB) * 4;   // 136 KB
    cudaFuncSetAttribute(persist_kernel,
                         cudaFuncAttributeMaxDynamicSharedMemorySize, SMEM);
    persist_kernel<<<NBLK, NTHR, SMEM>>>(b1, b2, out);
}